// round 1
// baseline (speedup 1.0000x reference)
#include <cuda_runtime.h>
#include <math.h>

#define CC   128
#define NPTS 4096
#define TN   32
#define OPT  16
#define EPSV 1e-12f

// Pre-expanded (se3) + transposed weights: Wt[c][o] = W[o][c]
__device__ float g_W1t [CC * CC];
__device__ float g_W2t [CC * CC];
__device__ float g_W3t [2 * CC * CC];
__device__ float g_svWt[CC * CC];
__device__ float g_vsdWt[CC * CC];
__device__ float g_vsWt[CC * CC];
__device__ float g_ssWt[CC * CC];

// ---------------------------------------------------------------------------
// Prep: expand se3 weights (append 1 - rowsum column) and transpose everything.
// grid = 128 blocks (one per output row o), 128 threads (column c).
// ---------------------------------------------------------------------------
__global__ void prep_kernel(const float* __restrict__ weight,        // [128,127]
                            const float* __restrict__ sv_W,          // [128,128]
                            const float* __restrict__ cross_weight,  // [128,127]
                            const float* __restrict__ crossfc_weight,// [128,255]
                            const float* __restrict__ vsdir_weight,  // [128,128]
                            const float* __restrict__ vs_W,          // [128,128]
                            const float* __restrict__ ss_W)          // [128,128]
{
    const int o = blockIdx.x;
    const int t = threadIdx.x;
    __shared__ float sred[128];

    // --- W1 = se3(weight) ---
    float w = (t < CC - 1) ? weight[o * (CC - 1) + t] : 0.f;
    sred[t] = w; __syncthreads();
    for (int k = 64; k > 0; k >>= 1) { if (t < k) sred[t] += sred[t + k]; __syncthreads(); }
    float rs1 = sred[0]; __syncthreads();
    if (t < CC - 1) g_W1t[t * CC + o] = w;
    else            g_W1t[(CC - 1) * CC + o] = 1.f - rs1;

    // --- W2 = se3(cross_weight) ---
    float w2 = (t < CC - 1) ? cross_weight[o * (CC - 1) + t] : 0.f;
    sred[t] = w2; __syncthreads();
    for (int k = 64; k > 0; k >>= 1) { if (t < k) sred[t] += sred[t + k]; __syncthreads(); }
    float rs2 = sred[0]; __syncthreads();
    if (t < CC - 1) g_W2t[t * CC + o] = w2;
    else            g_W2t[(CC - 1) * CC + o] = 1.f - rs2;

    // --- W3 = se3(crossfc_weight [128,255]) -> [256,128] transposed ---
    float a0 = crossfc_weight[o * (2 * CC - 1) + t];
    float a1 = (t < CC - 1) ? crossfc_weight[o * (2 * CC - 1) + CC + t] : 0.f;
    sred[t] = a0 + a1; __syncthreads();
    for (int k = 64; k > 0; k >>= 1) { if (t < k) sred[t] += sred[t + k]; __syncthreads(); }
    float rs3 = sred[0]; __syncthreads();
    g_W3t[t * CC + o] = a0;
    if (t < CC - 1) g_W3t[(CC + t) * CC + o] = a1;
    else            g_W3t[(2 * CC - 1) * CC + o] = 1.f - rs3;

    // --- plain transposes ---
    g_svWt [t * CC + o] = sv_W        [o * CC + t];
    g_vsdWt[t * CC + o] = vsdir_weight[o * CC + t];
    g_vsWt [t * CC + o] = vs_W        [o * CC + t];
    g_ssWt [t * CC + o] = ss_W        [o * CC + t];
}

// Load 16 consecutive transposed-weight floats (warp-uniform address) as 4x float4.
__device__ __forceinline__ void load_w16(const float* __restrict__ base, float* wv)
{
    const float4* wr = (const float4*)base;
    float4 a = wr[0], b = wr[1], c = wr[2], d = wr[3];
    wv[0]  = a.x; wv[1]  = a.y; wv[2]  = a.z; wv[3]  = a.w;
    wv[4]  = b.x; wv[5]  = b.y; wv[6]  = b.z; wv[7]  = b.w;
    wv[8]  = c.x; wv[9]  = c.y; wv[10] = c.z; wv[11] = c.w;
    wv[12] = d.x; wv[13] = d.y; wv[14] = d.z; wv[15] = d.w;
}

// ---------------------------------------------------------------------------
// Fused kernel: one block = one (b, 32-column) tile. 256 threads:
//   nl = tid & 31  -> column within tile
//   og = tid >> 5  -> output-channel group (16 channels per thread)
// ---------------------------------------------------------------------------
__global__ void __launch_bounds__(256)
fused_kernel(const float* __restrict__ v_in, const float* __restrict__ s_in,
             const float* __restrict__ sv_b, const float* __restrict__ vs_b,
             const float* __restrict__ ss_b, float* __restrict__ out, int B)
{
    extern __shared__ float sm[];
    float* sx  = sm;                 // [384][32]  x tile (later v_sR)
    float* su  = sm + 3 * CC * TN;   // [384][32]  v1
    float* sd  = sm + 6 * CC * TN;   // [384][32]  dual / v_cross / p
    float* ssc = sm + 9 * CC * TN;   // [128][32]  s tile
    float* red = ssc + CC * TN;      // [8][6][32] reduction scratch

    const int tid = threadIdx.x;
    const int nl  = tid & 31;
    const int og  = tid >> 5;
    const int ob  = og * OPT;

    const int b  = blockIdx.x >> 7;          // NPTS/TN = 128 blocks per batch
    const int n0 = (blockIdx.x & 127) * TN;

    // ---- load tiles (coalesced over n) ----
    {
        const float* src = v_in + ((size_t)b * (3 * CC)) * NPTS + n0 + nl;
        #pragma unroll
        for (int it = 0; it < 48; it++) {
            int r = og + it * 8;
            sx[r * TN + nl] = src[(size_t)r * NPTS];
        }
        const float* ssrc = s_in + ((size_t)b * CC) * NPTS + n0 + nl;
        #pragma unroll
        for (int it = 0; it < 16; it++) {
            int r = og + it * 8;
            ssc[r * TN + nl] = ssrc[(size_t)r * NPTS];
        }
    }
    __syncthreads();

    // ---- t = sv_W @ s + sv_b  (pre-normalize s2v) ----
    float tv[OPT];
    #pragma unroll
    for (int j = 0; j < OPT; j++) tv[j] = sv_b[ob + j];
    #pragma unroll 2
    for (int c = 0; c < CC; c++) {
        float s = ssc[c * TN + nl];
        float wv[16]; load_w16(&g_svWt[c * CC + ob], wv);
        #pragma unroll
        for (int j = 0; j < OPT; j++) tv[j] = fmaf(wv[j], s, tv[j]);
    }

    // ---- u = se3(weight) @ x ----
    float ux[OPT], uy[OPT], uz[OPT];
    #pragma unroll
    for (int j = 0; j < OPT; j++) { ux[j] = 0.f; uy[j] = 0.f; uz[j] = 0.f; }
    #pragma unroll 2
    for (int c = 0; c < CC; c++) {
        float xx = sx[(3 * c + 0) * TN + nl];
        float xy = sx[(3 * c + 1) * TN + nl];
        float xz = sx[(3 * c + 2) * TN + nl];
        float wv[16]; load_w16(&g_W1t[c * CC + ob], wv);
        #pragma unroll
        for (int j = 0; j < OPT; j++) {
            ux[j] = fmaf(wv[j], xx, ux[j]);
            uy[j] = fmaf(wv[j], xy, uy[j]);
            uz[j] = fmaf(wv[j], xz, uz[j]);
        }
    }

    // ---- reduce: channel-mean of u (3) + sumsq of t (1) ----
    {
        float px = 0, py = 0, pz = 0, pt = 0;
        #pragma unroll
        for (int j = 0; j < OPT; j++) { px += ux[j]; py += uy[j]; pz += uz[j]; pt += tv[j] * tv[j]; }
        red[(og * 6 + 0) * TN + nl] = px; red[(og * 6 + 1) * TN + nl] = py;
        red[(og * 6 + 2) * TN + nl] = pz; red[(og * 6 + 3) * TN + nl] = pt;
    }
    __syncthreads();
    float vmx = 0, vmy = 0, vmz = 0, tss = 0;
    #pragma unroll
    for (int g = 0; g < 8; g++) {
        vmx += red[(g * 6 + 0) * TN + nl]; vmy += red[(g * 6 + 1) * TN + nl];
        vmz += red[(g * 6 + 2) * TN + nl]; tss += red[(g * 6 + 3) * TN + nl];
    }
    __syncthreads();
    vmx *= (1.f / CC); vmy *= (1.f / CC); vmz *= (1.f / CC);
    const float tinv = 1.f / fmaxf(sqrtf(tss), EPSV);

    // ---- v1 = (u - vm) * s2v + vm ; keep in regs + smem; partial v1-mean ----
    float v1x[OPT], v1y[OPT], v1z[OPT];
    float p1x = 0, p1y = 0, p1z = 0;
    #pragma unroll
    for (int j = 0; j < OPT; j++) {
        float s2v = tv[j] * tinv;
        float ax = fmaf(ux[j] - vmx, s2v, vmx);
        float ay = fmaf(uy[j] - vmy, s2v, vmy);
        float az = fmaf(uz[j] - vmz, s2v, vmz);
        v1x[j] = ax; v1y[j] = ay; v1z[j] = az;
        int o = ob + j;
        su[(3 * o + 0) * TN + nl] = ax;
        su[(3 * o + 1) * TN + nl] = ay;
        su[(3 * o + 2) * TN + nl] = az;
        p1x += ax; p1y += ay; p1z += az;
    }
    __syncthreads();

    // ---- d = se3(cross_weight) @ x ----
    #pragma unroll
    for (int j = 0; j < OPT; j++) { ux[j] = 0.f; uy[j] = 0.f; uz[j] = 0.f; }
    #pragma unroll 2
    for (int c = 0; c < CC; c++) {
        float xx = sx[(3 * c + 0) * TN + nl];
        float xy = sx[(3 * c + 1) * TN + nl];
        float xz = sx[(3 * c + 2) * TN + nl];
        float wv[16]; load_w16(&g_W2t[c * CC + ob], wv);
        #pragma unroll
        for (int j = 0; j < OPT; j++) {
            ux[j] = fmaf(wv[j], xx, ux[j]);
            uy[j] = fmaf(wv[j], xy, uy[j]);
            uz[j] = fmaf(wv[j], xz, uz[j]);
        }
    }

    // ---- reduce: d-mean (3) + v1-mean (3) ----
    {
        float px = 0, py = 0, pz = 0;
        #pragma unroll
        for (int j = 0; j < OPT; j++) { px += ux[j]; py += uy[j]; pz += uz[j]; }
        red[(og * 6 + 0) * TN + nl] = px;  red[(og * 6 + 1) * TN + nl] = py;
        red[(og * 6 + 2) * TN + nl] = pz;  red[(og * 6 + 3) * TN + nl] = p1x;
        red[(og * 6 + 4) * TN + nl] = p1y; red[(og * 6 + 5) * TN + nl] = p1z;
    }
    __syncthreads();
    float dmx = 0, dmy = 0, dmz = 0, m1x = 0, m1y = 0, m1z = 0;
    #pragma unroll
    for (int g = 0; g < 8; g++) {
        dmx += red[(g * 6 + 0) * TN + nl]; dmy += red[(g * 6 + 1) * TN + nl];
        dmz += red[(g * 6 + 2) * TN + nl]; m1x += red[(g * 6 + 3) * TN + nl];
        m1y += red[(g * 6 + 4) * TN + nl]; m1z += red[(g * 6 + 5) * TN + nl];
    }
    __syncthreads();
    dmx *= (1.f / CC); dmy *= (1.f / CC); dmz *= (1.f / CC);
    m1x *= (1.f / CC); m1y *= (1.f / CC); m1z *= (1.f / CC);

    // ---- y = d - dm; per-channel norms; sumsq over channels ----
    float ny[OPT];
    {
        float pl = 0;
        #pragma unroll
        for (int j = 0; j < OPT; j++) {
            ux[j] -= dmx; uy[j] -= dmy; uz[j] -= dmz;
            float n2 = ux[j] * ux[j] + uy[j] * uy[j] + uz[j] * uz[j];
            ny[j] = sqrtf(n2);
            pl += n2;
        }
        red[og * TN + nl] = pl;
    }
    __syncthreads();
    float L = 0;
    #pragma unroll
    for (int g = 0; g < 8; g++) L += red[g * TN + nl];
    __syncthreads();
    const float linv = 1.f / fmaxf(sqrtf(L), EPSV);

    // ---- ceq = dir * nn ; v_cross = cross(ceq, v1 - v1m) + v1 -> sd ----
    #pragma unroll
    for (int j = 0; j < OPT; j++) {
        float cf = (ny[j] * linv) / fmaxf(ny[j], EPSV); // (nn / max(ny,eps)) applied to y
        float ex = ux[j] * cf, ey = uy[j] * cf, ez = uz[j] * cf;
        float wx = v1x[j] - m1x, wy = v1y[j] - m1y, wz = v1z[j] - m1z;
        float cx = ey * wz - ez * wy + v1x[j];
        float cy = ez * wx - ex * wz + v1y[j];
        float cz = ex * wy - ey * wx + v1z[j];
        int o = ob + j;
        sd[(3 * o + 0) * TN + nl] = cx;
        sd[(3 * o + 1) * TN + nl] = cy;
        sd[(3 * o + 2) * TN + nl] = cz;
    }
    __syncthreads();

    // ---- v_out = se3(crossfc)[:, :128] @ v_cross + [:, 128:] @ v1 ----
    #pragma unroll
    for (int j = 0; j < OPT; j++) { ux[j] = 0.f; uy[j] = 0.f; uz[j] = 0.f; }
    #pragma unroll 2
    for (int c = 0; c < CC; c++) {
        float xx = sd[(3 * c + 0) * TN + nl];
        float xy = sd[(3 * c + 1) * TN + nl];
        float xz = sd[(3 * c + 2) * TN + nl];
        float wv[16]; load_w16(&g_W3t[c * CC + ob], wv);
        #pragma unroll
        for (int j = 0; j < OPT; j++) {
            ux[j] = fmaf(wv[j], xx, ux[j]);
            uy[j] = fmaf(wv[j], xy, uy[j]);
            uz[j] = fmaf(wv[j], xz, uz[j]);
        }
    }
    #pragma unroll 2
    for (int c = 0; c < CC; c++) {
        float xx = su[(3 * c + 0) * TN + nl];
        float xy = su[(3 * c + 1) * TN + nl];
        float xz = su[(3 * c + 2) * TN + nl];
        float wv[16]; load_w16(&g_W3t[(CC + c) * CC + ob], wv);
        #pragma unroll
        for (int j = 0; j < OPT; j++) {
            ux[j] = fmaf(wv[j], xx, ux[j]);
            uy[j] = fmaf(wv[j], xy, uy[j]);
            uz[j] = fmaf(wv[j], xz, uz[j]);
        }
    }
    {
        float* outv = out + ((size_t)b * CC) * 3 * NPTS + n0 + nl;
        #pragma unroll
        for (int j = 0; j < OPT; j++) {
            int o = ob + j;
            outv[(size_t)(3 * o + 0) * NPTS] = ux[j];
            outv[(size_t)(3 * o + 1) * NPTS] = uy[j];
            outv[(size_t)(3 * o + 2) * NPTS] = uz[j];
        }
    }

    // ================= scalar branch =================
    // ---- x channel mean; v_sR = x - mean (in place in sx) ----
    {
        float px = 0, py = 0, pz = 0;
        #pragma unroll
        for (int j = 0; j < OPT; j++) {
            int c2 = ob + j;
            px += sx[(3 * c2 + 0) * TN + nl];
            py += sx[(3 * c2 + 1) * TN + nl];
            pz += sx[(3 * c2 + 2) * TN + nl];
        }
        red[(og * 3 + 0) * TN + nl] = px;
        red[(og * 3 + 1) * TN + nl] = py;
        red[(og * 3 + 2) * TN + nl] = pz;
    }
    __syncthreads();
    float xmx = 0, xmy = 0, xmz = 0;
    #pragma unroll
    for (int g = 0; g < 8; g++) {
        xmx += red[(g * 3 + 0) * TN + nl];
        xmy += red[(g * 3 + 1) * TN + nl];
        xmz += red[(g * 3 + 2) * TN + nl];
    }
    __syncthreads();
    xmx *= (1.f / CC); xmy *= (1.f / CC); xmz *= (1.f / CC);
    #pragma unroll
    for (int j = 0; j < OPT; j++) {
        int c2 = ob + j;
        sx[(3 * c2 + 0) * TN + nl] -= xmx;
        sx[(3 * c2 + 1) * TN + nl] -= xmy;
        sx[(3 * c2 + 2) * TN + nl] -= xmz;
    }
    __syncthreads();

    // ---- dd = vsdir_weight @ v_sR ; q_o = v_sR_o . normalize(dd_o) ----
    #pragma unroll
    for (int j = 0; j < OPT; j++) { ux[j] = 0.f; uy[j] = 0.f; uz[j] = 0.f; }
    #pragma unroll 2
    for (int c = 0; c < CC; c++) {
        float xx = sx[(3 * c + 0) * TN + nl];
        float xy = sx[(3 * c + 1) * TN + nl];
        float xz = sx[(3 * c + 2) * TN + nl];
        float wv[16]; load_w16(&g_vsdWt[c * CC + ob], wv);
        #pragma unroll
        for (int j = 0; j < OPT; j++) {
            ux[j] = fmaf(wv[j], xx, ux[j]);
            uy[j] = fmaf(wv[j], xy, uy[j]);
            uz[j] = fmaf(wv[j], xz, uz[j]);
        }
    }
    {
        float pq = 0;
        #pragma unroll
        for (int j = 0; j < OPT; j++) {
            float n2 = ux[j] * ux[j] + uy[j] * uy[j] + uz[j] * uz[j];
            float inv = 1.f / fmaxf(sqrtf(n2), EPSV);
            int o = ob + j;
            float q = (sx[(3 * o + 0) * TN + nl] * ux[j] +
                       sx[(3 * o + 1) * TN + nl] * uy[j] +
                       sx[(3 * o + 2) * TN + nl] * uz[j]) * inv;
            tv[j] = q;
            pq += q * q;
        }
        red[og * TN + nl] = pq;
    }
    __syncthreads();
    float Q = 0;
    #pragma unroll
    for (int g = 0; g < 8; g++) Q += red[g * TN + nl];
    __syncthreads();
    const float qinv = 1.f / fmaxf(sqrtf(Q), EPSV);
    #pragma unroll
    for (int j = 0; j < OPT; j++)
        sd[(ob + j) * TN + nl] = tv[j] * qinv;   // p (normalized s_from_v)
    __syncthreads();

    // ---- s_out = vs_W @ p + vs_b + ss_W @ s + ss_b ----
    float so[OPT];
    #pragma unroll
    for (int j = 0; j < OPT; j++) so[j] = vs_b[ob + j] + ss_b[ob + j];
    #pragma unroll 2
    for (int c = 0; c < CC; c++) {
        float p = sd[c * TN + nl];
        float s = ssc[c * TN + nl];
        float wv [16]; load_w16(&g_vsWt[c * CC + ob], wv);
        float wv2[16]; load_w16(&g_ssWt[c * CC + ob], wv2);
        #pragma unroll
        for (int j = 0; j < OPT; j++)
            so[j] = fmaf(wv[j], p, fmaf(wv2[j], s, so[j]));
    }
    {
        float* outs = out + (size_t)B * CC * 3 * NPTS + ((size_t)b * CC) * NPTS + n0 + nl;
        #pragma unroll
        for (int j = 0; j < OPT; j++)
            outs[(size_t)(ob + j) * NPTS] = so[j];
    }
}

extern "C" void kernel_launch(void* const* d_in, const int* in_sizes, int n_in,
                              void* d_out, int out_size)
{
    const float* v_in      = (const float*)d_in[0];
    const float* s_in      = (const float*)d_in[1];
    const float* weight    = (const float*)d_in[2];
    const float* sv_W      = (const float*)d_in[3];
    const float* sv_b      = (const float*)d_in[4];
    const float* cross_w   = (const float*)d_in[5];
    const float* crossfc_w = (const float*)d_in[6];
    const float* vsdir_w   = (const float*)d_in[7];
    const float* vs_W      = (const float*)d_in[8];
    const float* vs_b      = (const float*)d_in[9];
    const float* ss_W      = (const float*)d_in[10];
    const float* ss_b      = (const float*)d_in[11];
    float* out = (float*)d_out;

    const int B = in_sizes[0] / (CC * 3 * NPTS);   // 16

    prep_kernel<<<CC, CC>>>(weight, sv_W, cross_w, crossfc_w, vsdir_w, vs_W, ss_W);

    const size_t smem = (size_t)(10 * CC * TN + 8 * 6 * TN) * sizeof(float); // 169,984 B
    cudaFuncSetAttribute(fused_kernel, cudaFuncAttributeMaxDynamicSharedMemorySize, (int)smem);
    fused_kernel<<<B * (NPTS / TN), 256, smem>>>(v_in, s_in, sv_b, vs_b, ss_b, out, B);
}

// round 2
// speedup vs baseline: 1.4426x; 1.4426x over previous
#include <cuda_runtime.h>
#include <math.h>

#define CC   128
#define NPTS 4096
#define TN   32
#define OPT  16
#define EPSV 1e-12f

// Pre-expanded (se3) + transposed weights: Wt[c][o] = W[o][c]
__device__ float g_W1t [CC * CC];
__device__ float g_W2t [CC * CC];
__device__ float g_W3t [2 * CC * CC];
__device__ float g_svWt[CC * CC];
__device__ float g_vsdWt[CC * CC];
__device__ float g_vsWt[CC * CC];
__device__ float g_ssWt[CC * CC];

// ---------------------------------------------------------------------------
// Prep: expand se3 weights (append 1 - rowsum column) and transpose everything.
// ---------------------------------------------------------------------------
__global__ void prep_kernel(const float* __restrict__ weight,        // [128,127]
                            const float* __restrict__ sv_W,          // [128,128]
                            const float* __restrict__ cross_weight,  // [128,127]
                            const float* __restrict__ crossfc_weight,// [128,255]
                            const float* __restrict__ vsdir_weight,  // [128,128]
                            const float* __restrict__ vs_W,          // [128,128]
                            const float* __restrict__ ss_W)          // [128,128]
{
    const int o = blockIdx.x;
    const int t = threadIdx.x;
    __shared__ float sred[128];

    // --- W1 = se3(weight) ---
    float w = (t < CC - 1) ? weight[o * (CC - 1) + t] : 0.f;
    sred[t] = w; __syncthreads();
    for (int k = 64; k > 0; k >>= 1) { if (t < k) sred[t] += sred[t + k]; __syncthreads(); }
    float rs1 = sred[0]; __syncthreads();
    if (t < CC - 1) g_W1t[t * CC + o] = w;
    else            g_W1t[(CC - 1) * CC + o] = 1.f - rs1;

    // --- W2 = se3(cross_weight) ---
    float w2 = (t < CC - 1) ? cross_weight[o * (CC - 1) + t] : 0.f;
    sred[t] = w2; __syncthreads();
    for (int k = 64; k > 0; k >>= 1) { if (t < k) sred[t] += sred[t + k]; __syncthreads(); }
    float rs2 = sred[0]; __syncthreads();
    if (t < CC - 1) g_W2t[t * CC + o] = w2;
    else            g_W2t[(CC - 1) * CC + o] = 1.f - rs2;

    // --- W3 = se3(crossfc_weight [128,255]) -> [256,128] transposed ---
    float a0 = crossfc_weight[o * (2 * CC - 1) + t];
    float a1 = (t < CC - 1) ? crossfc_weight[o * (2 * CC - 1) + CC + t] : 0.f;
    sred[t] = a0 + a1; __syncthreads();
    for (int k = 64; k > 0; k >>= 1) { if (t < k) sred[t] += sred[t + k]; __syncthreads(); }
    float rs3 = sred[0]; __syncthreads();
    g_W3t[t * CC + o] = a0;
    if (t < CC - 1) g_W3t[(CC + t) * CC + o] = a1;
    else            g_W3t[(2 * CC - 1) * CC + o] = 1.f - rs3;

    // --- plain transposes ---
    g_svWt [t * CC + o] = sv_W        [o * CC + t];
    g_vsdWt[t * CC + o] = vsdir_weight[o * CC + t];
    g_vsWt [t * CC + o] = vs_W        [o * CC + t];
    g_ssWt [t * CC + o] = ss_W        [o * CC + t];
}

// Load 16 consecutive transposed-weight floats (warp-uniform address) as 4x float4.
__device__ __forceinline__ void load_w16(const float* __restrict__ base, float* wv)
{
    const float4* wr = (const float4*)base;
    float4 a = wr[0], b = wr[1], c = wr[2], d = wr[3];
    wv[0]  = a.x; wv[1]  = a.y; wv[2]  = a.z; wv[3]  = a.w;
    wv[4]  = b.x; wv[5]  = b.y; wv[6]  = b.z; wv[7]  = b.w;
    wv[8]  = c.x; wv[9]  = c.y; wv[10] = c.z; wv[11] = c.w;
    wv[12] = d.x; wv[13] = d.y; wv[14] = d.z; wv[15] = d.w;
}

// ---------------------------------------------------------------------------
// Fused kernel: one block = one (b, 32-column) tile. 256 threads, 2 blocks/SM.
// smem: A[384][32] (x_c, later v_cross), B[384][32] (s+p, later v1), R[48][32].
// ---------------------------------------------------------------------------
__global__ void __launch_bounds__(256, 2)
fused_kernel(const float* __restrict__ v_in, const float* __restrict__ s_in,
             const float* __restrict__ sv_b, const float* __restrict__ vs_b,
             const float* __restrict__ ss_b, float* __restrict__ out, int B)
{
    extern __shared__ float sm[];
    float* A   = sm;                     // [384][32]
    float* Bm  = sm + 3 * CC * TN;       // [384][32]
    float* red = sm + 6 * CC * TN;       // [48][32]

    const int tid = threadIdx.x;
    const int nl  = tid & 31;
    const int og  = tid >> 5;
    const int ob  = og * OPT;

    const int b  = blockIdx.x >> 7;
    const int n0 = (blockIdx.x & 127) * TN;

    // ---- load x -> A, s -> Bm[0:128] ----
    {
        const float* src = v_in + ((size_t)b * (3 * CC)) * NPTS + n0 + nl;
        #pragma unroll
        for (int it = 0; it < 48; it++) {
            int r = og + it * 8;
            A[r * TN + nl] = src[(size_t)r * NPTS];
        }
        const float* ssrc = s_in + ((size_t)b * CC) * NPTS + n0 + nl;
        #pragma unroll
        for (int it = 0; it < 16; it++) {
            int r = og + it * 8;
            Bm[r * TN + nl] = ssrc[(size_t)r * NPTS];
        }
    }
    __syncthreads();

    // ---- x channel mean; center A in place (x_c = v_sR) ----
    float mx, my, mz;
    {
        float px = 0, py = 0, pz = 0;
        #pragma unroll
        for (int j = 0; j < OPT; j++) {
            int c = ob + j;
            px += A[(3 * c + 0) * TN + nl];
            py += A[(3 * c + 1) * TN + nl];
            pz += A[(3 * c + 2) * TN + nl];
        }
        red[(og * 6 + 0) * TN + nl] = px;
        red[(og * 6 + 1) * TN + nl] = py;
        red[(og * 6 + 2) * TN + nl] = pz;
    }
    __syncthreads();
    mx = 0; my = 0; mz = 0;
    #pragma unroll
    for (int g = 0; g < 8; g++) {
        mx += red[(g * 6 + 0) * TN + nl];
        my += red[(g * 6 + 1) * TN + nl];
        mz += red[(g * 6 + 2) * TN + nl];
    }
    __syncthreads();
    mx *= (1.f / CC); my *= (1.f / CC); mz *= (1.f / CC);
    #pragma unroll
    for (int j = 0; j < OPT; j++) {
        int c = ob + j;
        A[(3 * c + 0) * TN + nl] -= mx;
        A[(3 * c + 1) * TN + nl] -= my;
        A[(3 * c + 2) * TN + nl] -= mz;
    }
    __syncthreads();

    float ux[OPT], uy[OPT], uz[OPT], tv[OPT];

    // ================= scalar branch (uses x_c and s only) =================
    // dd = vsdir_weight @ x_c
    #pragma unroll
    for (int j = 0; j < OPT; j++) { ux[j] = 0.f; uy[j] = 0.f; uz[j] = 0.f; }
    #pragma unroll 2
    for (int c = 0; c < CC; c++) {
        float xx = A[(3 * c + 0) * TN + nl];
        float xy = A[(3 * c + 1) * TN + nl];
        float xz = A[(3 * c + 2) * TN + nl];
        float wv[16]; load_w16(&g_vsdWt[c * CC + ob], wv);
        #pragma unroll
        for (int j = 0; j < OPT; j++) {
            ux[j] = fmaf(wv[j], xx, ux[j]);
            uy[j] = fmaf(wv[j], xy, uy[j]);
            uz[j] = fmaf(wv[j], xz, uz[j]);
        }
    }
    {
        float pq = 0;
        #pragma unroll
        for (int j = 0; j < OPT; j++) {
            float n2 = ux[j] * ux[j] + uy[j] * uy[j] + uz[j] * uz[j];
            float inv = 1.f / fmaxf(sqrtf(n2), EPSV);
            int o = ob + j;
            float q = (A[(3 * o + 0) * TN + nl] * ux[j] +
                       A[(3 * o + 1) * TN + nl] * uy[j] +
                       A[(3 * o + 2) * TN + nl] * uz[j]) * inv;
            tv[j] = q;
            pq += q * q;
        }
        red[og * TN + nl] = pq;
    }
    __syncthreads();
    float Q = 0;
    #pragma unroll
    for (int g = 0; g < 8; g++) Q += red[g * TN + nl];
    __syncthreads();
    const float qinv = 1.f / fmaxf(sqrtf(Q), EPSV);
    #pragma unroll
    for (int j = 0; j < OPT; j++)
        Bm[(CC + ob + j) * TN + nl] = tv[j] * qinv;   // p in Bm rows [128,256)
    __syncthreads();

    // s_out = vs_W @ p + vs_b + ss_W @ s + ss_b
    {
        float so[OPT];
        #pragma unroll
        for (int j = 0; j < OPT; j++) so[j] = vs_b[ob + j] + ss_b[ob + j];
        #pragma unroll 2
        for (int c = 0; c < CC; c++) {
            float p = Bm[(CC + c) * TN + nl];
            float s = Bm[c * TN + nl];
            float wv [16]; load_w16(&g_vsWt[c * CC + ob], wv);
            float wv2[16]; load_w16(&g_ssWt[c * CC + ob], wv2);
            #pragma unroll
            for (int j = 0; j < OPT; j++)
                so[j] = fmaf(wv[j], p, fmaf(wv2[j], s, so[j]));
        }
        float* outs = out + (size_t)B * CC * 3 * NPTS + ((size_t)b * CC) * NPTS + n0 + nl;
        #pragma unroll
        for (int j = 0; j < OPT; j++)
            outs[(size_t)(ob + j) * NPTS] = so[j];
    }

    // ---- t = sv_W @ s + sv_b (last reader of s region) ----
    #pragma unroll
    for (int j = 0; j < OPT; j++) tv[j] = sv_b[ob + j];
    #pragma unroll 2
    for (int c = 0; c < CC; c++) {
        float s = Bm[c * TN + nl];
        float wv[16]; load_w16(&g_svWt[c * CC + ob], wv);
        #pragma unroll
        for (int j = 0; j < OPT; j++) tv[j] = fmaf(wv[j], s, tv[j]);
    }

    // ================= vector branch =================
    // ---- u_c = W1 @ x_c ----
    #pragma unroll
    for (int j = 0; j < OPT; j++) { ux[j] = 0.f; uy[j] = 0.f; uz[j] = 0.f; }
    #pragma unroll 2
    for (int c = 0; c < CC; c++) {
        float xx = A[(3 * c + 0) * TN + nl];
        float xy = A[(3 * c + 1) * TN + nl];
        float xz = A[(3 * c + 2) * TN + nl];
        float wv[16]; load_w16(&g_W1t[c * CC + ob], wv);
        #pragma unroll
        for (int j = 0; j < OPT; j++) {
            ux[j] = fmaf(wv[j], xx, ux[j]);
            uy[j] = fmaf(wv[j], xy, uy[j]);
            uz[j] = fmaf(wv[j], xz, uz[j]);
        }
    }
    // reduce: mean of u_c (3) + sumsq of t (1)
    {
        float px = 0, py = 0, pz = 0, pt = 0;
        #pragma unroll
        for (int j = 0; j < OPT; j++) { px += ux[j]; py += uy[j]; pz += uz[j]; pt += tv[j] * tv[j]; }
        red[(og * 6 + 0) * TN + nl] = px; red[(og * 6 + 1) * TN + nl] = py;
        red[(og * 6 + 2) * TN + nl] = pz; red[(og * 6 + 3) * TN + nl] = pt;
    }
    __syncthreads();   // also: all reads of s/p in Bm are complete after this
    float mux = 0, muy = 0, muz = 0, tss = 0;
    #pragma unroll
    for (int g = 0; g < 8; g++) {
        mux += red[(g * 6 + 0) * TN + nl]; muy += red[(g * 6 + 1) * TN + nl];
        muz += red[(g * 6 + 2) * TN + nl]; tss += red[(g * 6 + 3) * TN + nl];
    }
    __syncthreads();
    mux *= (1.f / CC); muy *= (1.f / CC); muz *= (1.f / CC);
    const float tinv = 1.f / fmaxf(sqrtf(tss), EPSV);

    // v1 = (u_c - mu)*s2v + (mu + m)  -> Bm (overwrites s/p); partial v1-mean
    float p1x = 0, p1y = 0, p1z = 0;
    #pragma unroll
    for (int j = 0; j < OPT; j++) {
        float s2v = tv[j] * tinv;
        float ax = fmaf(ux[j] - mux, s2v, mux + mx);
        float ay = fmaf(uy[j] - muy, s2v, muy + my);
        float az = fmaf(uz[j] - muz, s2v, muz + mz);
        int o = ob + j;
        Bm[(3 * o + 0) * TN + nl] = ax;
        Bm[(3 * o + 1) * TN + nl] = ay;
        Bm[(3 * o + 2) * TN + nl] = az;
        p1x += ax; p1y += ay; p1z += az;
    }

    // ---- d_c = W2 @ x_c (mean-shift cancels in d - d_mean) ----
    #pragma unroll
    for (int j = 0; j < OPT; j++) { ux[j] = 0.f; uy[j] = 0.f; uz[j] = 0.f; }
    #pragma unroll 2
    for (int c = 0; c < CC; c++) {
        float xx = A[(3 * c + 0) * TN + nl];
        float xy = A[(3 * c + 1) * TN + nl];
        float xz = A[(3 * c + 2) * TN + nl];
        float wv[16]; load_w16(&g_W2t[c * CC + ob], wv);
        #pragma unroll
        for (int j = 0; j < OPT; j++) {
            ux[j] = fmaf(wv[j], xx, ux[j]);
            uy[j] = fmaf(wv[j], xy, uy[j]);
            uz[j] = fmaf(wv[j], xz, uz[j]);
        }
    }
    // reduce: d mean (3) + v1 mean (3)
    {
        float px = 0, py = 0, pz = 0;
        #pragma unroll
        for (int j = 0; j < OPT; j++) { px += ux[j]; py += uy[j]; pz += uz[j]; }
        red[(og * 6 + 0) * TN + nl] = px;  red[(og * 6 + 1) * TN + nl] = py;
        red[(og * 6 + 2) * TN + nl] = pz;  red[(og * 6 + 3) * TN + nl] = p1x;
        red[(og * 6 + 4) * TN + nl] = p1y; red[(og * 6 + 5) * TN + nl] = p1z;
    }
    __syncthreads();
    float dmx = 0, dmy = 0, dmz = 0, m1x = 0, m1y = 0, m1z = 0;
    #pragma unroll
    for (int g = 0; g < 8; g++) {
        dmx += red[(g * 6 + 0) * TN + nl]; dmy += red[(g * 6 + 1) * TN + nl];
        dmz += red[(g * 6 + 2) * TN + nl]; m1x += red[(g * 6 + 3) * TN + nl];
        m1y += red[(g * 6 + 4) * TN + nl]; m1z += red[(g * 6 + 5) * TN + nl];
    }
    __syncthreads();
    dmx *= (1.f / CC); dmy *= (1.f / CC); dmz *= (1.f / CC);
    m1x *= (1.f / CC); m1y *= (1.f / CC); m1z *= (1.f / CC);

    // ---- y = d_c - dm; norms; sumsq over channels ----
    float ny[OPT];
    {
        float pl = 0;
        #pragma unroll
        for (int j = 0; j < OPT; j++) {
            ux[j] -= dmx; uy[j] -= dmy; uz[j] -= dmz;
            float n2 = ux[j] * ux[j] + uy[j] * uy[j] + uz[j] * uz[j];
            ny[j] = sqrtf(n2);
            pl += n2;
        }
        red[og * TN + nl] = pl;
    }
    __syncthreads();
    float L = 0;
    #pragma unroll
    for (int g = 0; g < 8; g++) L += red[g * TN + nl];
    __syncthreads();
    const float linv = 1.f / fmaxf(sqrtf(L), EPSV);

    // ---- v_cross = cross(ceq, v1 - v1m) + v1 -> A (x_c dead) ----
    #pragma unroll
    for (int j = 0; j < OPT; j++) {
        float cf = (ny[j] * linv) / fmaxf(ny[j], EPSV);
        float ex = ux[j] * cf, ey = uy[j] * cf, ez = uz[j] * cf;
        int o = ob + j;
        float ax = Bm[(3 * o + 0) * TN + nl];
        float ay = Bm[(3 * o + 1) * TN + nl];
        float az = Bm[(3 * o + 2) * TN + nl];
        float wx = ax - m1x, wy = ay - m1y, wz = az - m1z;
        A[(3 * o + 0) * TN + nl] = ey * wz - ez * wy + ax;
        A[(3 * o + 1) * TN + nl] = ez * wx - ex * wz + ay;
        A[(3 * o + 2) * TN + nl] = ex * wy - ey * wx + az;
    }
    __syncthreads();

    // ---- v_out = W3[:, :128] @ v_cross (A) + W3[:, 128:] @ v1 (Bm) ----
    #pragma unroll
    for (int j = 0; j < OPT; j++) { ux[j] = 0.f; uy[j] = 0.f; uz[j] = 0.f; }
    #pragma unroll 2
    for (int c = 0; c < CC; c++) {
        float xx = A[(3 * c + 0) * TN + nl];
        float xy = A[(3 * c + 1) * TN + nl];
        float xz = A[(3 * c + 2) * TN + nl];
        float wv[16]; load_w16(&g_W3t[c * CC + ob], wv);
        #pragma unroll
        for (int j = 0; j < OPT; j++) {
            ux[j] = fmaf(wv[j], xx, ux[j]);
            uy[j] = fmaf(wv[j], xy, uy[j]);
            uz[j] = fmaf(wv[j], xz, uz[j]);
        }
    }
    #pragma unroll 2
    for (int c = 0; c < CC; c++) {
        float xx = Bm[(3 * c + 0) * TN + nl];
        float xy = Bm[(3 * c + 1) * TN + nl];
        float xz = Bm[(3 * c + 2) * TN + nl];
        float wv[16]; load_w16(&g_W3t[(CC + c) * CC + ob], wv);
        #pragma unroll
        for (int j = 0; j < OPT; j++) {
            ux[j] = fmaf(wv[j], xx, ux[j]);
            uy[j] = fmaf(wv[j], xy, uy[j]);
            uz[j] = fmaf(wv[j], xz, uz[j]);
        }
    }
    {
        float* outv = out + ((size_t)b * CC) * 3 * NPTS + n0 + nl;
        #pragma unroll
        for (int j = 0; j < OPT; j++) {
            int o = ob + j;
            outv[(size_t)(3 * o + 0) * NPTS] = ux[j];
            outv[(size_t)(3 * o + 1) * NPTS] = uy[j];
            outv[(size_t)(3 * o + 2) * NPTS] = uz[j];
        }
    }
}

extern "C" void kernel_launch(void* const* d_in, const int* in_sizes, int n_in,
                              void* d_out, int out_size)
{
    const float* v_in      = (const float*)d_in[0];
    const float* s_in      = (const float*)d_in[1];
    const float* weight    = (const float*)d_in[2];
    const float* sv_W      = (const float*)d_in[3];
    const float* sv_b      = (const float*)d_in[4];
    const float* cross_w   = (const float*)d_in[5];
    const float* crossfc_w = (const float*)d_in[6];
    const float* vsdir_w   = (const float*)d_in[7];
    const float* vs_W      = (const float*)d_in[8];
    const float* vs_b      = (const float*)d_in[9];
    const float* ss_W      = (const float*)d_in[10];
    const float* ss_b      = (const float*)d_in[11];
    float* out = (float*)d_out;

    const int B = in_sizes[0] / (CC * 3 * NPTS);   // 16

    prep_kernel<<<CC, CC>>>(weight, sv_W, cross_w, crossfc_w, vsdir_w, vs_W, ss_W);

    const size_t smem = (size_t)(6 * CC * TN + 48 * TN) * sizeof(float); // 104,448 B
    cudaFuncSetAttribute(fused_kernel, cudaFuncAttributeMaxDynamicSharedMemorySize, (int)smem);
    fused_kernel<<<B * (NPTS / TN), 256, smem>>>(v_in, s_in, sv_b, vs_b, ss_b, out, B);
}

// round 6
// speedup vs baseline: 1.5889x; 1.1014x over previous
#include <cuda_runtime.h>
#include <math.h>
#include <stdint.h>

#define CC   128
#define NPTS 4096
#define TN   32
#define OPT  16
#define OP2  8
#define EPSV 1e-12f

// Pre-expanded (se3) + transposed weights: Wt[c][o] = W[o][c]
__device__ float g_W1t [CC * CC];
__device__ float g_W2t [CC * CC];
__device__ float g_W3t [2 * CC * CC];
__device__ float g_svWt[CC * CC];
__device__ float g_vsdWt[CC * CC];
__device__ float g_vsWt[CC * CC];
__device__ float g_ssWt[CC * CC];

// ---------------------------------------------------------------------------
// Prep: expand se3 weights (append 1 - rowsum column) and transpose everything.
// ---------------------------------------------------------------------------
__global__ void prep_kernel(const float* __restrict__ weight,        // [128,127]
                            const float* __restrict__ sv_W,          // [128,128]
                            const float* __restrict__ cross_weight,  // [128,127]
                            const float* __restrict__ crossfc_weight,// [128,255]
                            const float* __restrict__ vsdir_weight,  // [128,128]
                            const float* __restrict__ vs_W,          // [128,128]
                            const float* __restrict__ ss_W)          // [128,128]
{
    const int o = blockIdx.x;
    const int t = threadIdx.x;
    __shared__ float sred[128];

    float w = (t < CC - 1) ? weight[o * (CC - 1) + t] : 0.f;
    sred[t] = w; __syncthreads();
    for (int k = 64; k > 0; k >>= 1) { if (t < k) sred[t] += sred[t + k]; __syncthreads(); }
    float rs1 = sred[0]; __syncthreads();
    if (t < CC - 1) g_W1t[t * CC + o] = w;
    else            g_W1t[(CC - 1) * CC + o] = 1.f - rs1;

    float w2 = (t < CC - 1) ? cross_weight[o * (CC - 1) + t] : 0.f;
    sred[t] = w2; __syncthreads();
    for (int k = 64; k > 0; k >>= 1) { if (t < k) sred[t] += sred[t + k]; __syncthreads(); }
    float rs2 = sred[0]; __syncthreads();
    if (t < CC - 1) g_W2t[t * CC + o] = w2;
    else            g_W2t[(CC - 1) * CC + o] = 1.f - rs2;

    float a0 = crossfc_weight[o * (2 * CC - 1) + t];
    float a1 = (t < CC - 1) ? crossfc_weight[o * (2 * CC - 1) + CC + t] : 0.f;
    sred[t] = a0 + a1; __syncthreads();
    for (int k = 64; k > 0; k >>= 1) { if (t < k) sred[t] += sred[t + k]; __syncthreads(); }
    float rs3 = sred[0]; __syncthreads();
    g_W3t[t * CC + o] = a0;
    if (t < CC - 1) g_W3t[(CC + t) * CC + o] = a1;
    else            g_W3t[(2 * CC - 1) * CC + o] = 1.f - rs3;

    g_svWt [t * CC + o] = sv_W        [o * CC + t];
    g_vsdWt[t * CC + o] = vsdir_weight[o * CC + t];
    g_vsWt [t * CC + o] = vs_W        [o * CC + t];
    g_ssWt [t * CC + o] = ss_W        [o * CC + t];
}

// ---- packed f32x2 helpers ----
#define FMA2(acc, w, x) \
    asm("fma.rn.f32x2 %0, %1, %2, %3;" : "=l"(acc) : "l"(w), "l"(x), "l"(acc))
#define PACK_DUP(out, x) \
    asm("mov.b64 %0, {%1, %1};" : "=l"(out) : "r"(__float_as_uint(x)))

__device__ __forceinline__ float lo2(unsigned long long v) { return __uint_as_float((unsigned)v); }
__device__ __forceinline__ float hi2(unsigned long long v) { return __uint_as_float((unsigned)(v >> 32)); }
__device__ __forceinline__ unsigned long long pack2(float lo, float hi) {
    return (unsigned long long)__float_as_uint(lo) |
           ((unsigned long long)__float_as_uint(hi) << 32);
}

// Load 16 consecutive transposed-weight floats as 8 packed u64 pairs (4x LDG.128).
__device__ __forceinline__ void load_w8x2(const float* __restrict__ base, unsigned long long* w2)
{
    const ulonglong2* p = (const ulonglong2*)base;
    ulonglong2 a = p[0], b = p[1], c = p[2], d = p[3];
    w2[0] = a.x; w2[1] = a.y; w2[2] = b.x; w2[3] = b.y;
    w2[4] = c.x; w2[5] = c.y; w2[6] = d.x; w2[7] = d.y;
}

// ---------------------------------------------------------------------------
// Fused kernel: one block = one (b, 32-column) tile. 256 threads, 2 blocks/SM.
// ---------------------------------------------------------------------------
__global__ void __launch_bounds__(256, 2)
fused_kernel(const float* __restrict__ v_in, const float* __restrict__ s_in,
             const float* __restrict__ sv_b, const float* __restrict__ vs_b,
             const float* __restrict__ ss_b, float* __restrict__ out, int B)
{
    extern __shared__ float sm[];
    float* A   = sm;                     // [384][32]  x_c, later v_cross
    float* Bm  = sm + 3 * CC * TN;       // [384][32]  s+p, later v1
    float* red = sm + 6 * CC * TN;       // [48][32]

    const int tid = threadIdx.x;
    const int nl  = tid & 31;
    const int og  = tid >> 5;
    const int ob  = og * OPT;

    const int b  = blockIdx.x >> 7;
    const int n0 = (blockIdx.x & 127) * TN;

    // ---- load x -> A, s -> Bm[0:128] ----
    {
        const float* src = v_in + ((size_t)b * (3 * CC)) * NPTS + n0 + nl;
        #pragma unroll
        for (int it = 0; it < 48; it++) {
            int r = og + it * 8;
            A[r * TN + nl] = src[(size_t)r * NPTS];
        }
        const float* ssrc = s_in + ((size_t)b * CC) * NPTS + n0 + nl;
        #pragma unroll
        for (int it = 0; it < 16; it++) {
            int r = og + it * 8;
            Bm[r * TN + nl] = ssrc[(size_t)r * NPTS];
        }
    }
    __syncthreads();

    // ---- x channel mean; center A in place ----
    float mx, my, mz;
    {
        float px = 0, py = 0, pz = 0;
        #pragma unroll
        for (int j = 0; j < OPT; j++) {
            int c = ob + j;
            px += A[(3 * c + 0) * TN + nl];
            py += A[(3 * c + 1) * TN + nl];
            pz += A[(3 * c + 2) * TN + nl];
        }
        red[(og * 6 + 0) * TN + nl] = px;
        red[(og * 6 + 1) * TN + nl] = py;
        red[(og * 6 + 2) * TN + nl] = pz;
    }
    __syncthreads();
    mx = 0; my = 0; mz = 0;
    #pragma unroll
    for (int g = 0; g < 8; g++) {
        mx += red[(g * 6 + 0) * TN + nl];
        my += red[(g * 6 + 1) * TN + nl];
        mz += red[(g * 6 + 2) * TN + nl];
    }
    __syncthreads();
    mx *= (1.f / CC); my *= (1.f / CC); mz *= (1.f / CC);
    #pragma unroll
    for (int j = 0; j < OPT; j++) {
        int c = ob + j;
        A[(3 * c + 0) * TN + nl] -= mx;
        A[(3 * c + 1) * TN + nl] -= my;
        A[(3 * c + 2) * TN + nl] -= mz;
    }
    __syncthreads();

    unsigned long long aX[OP2], aY[OP2], aZ[OP2];
    float ux[OPT], uy[OPT], uz[OPT], tv[OPT];

    // ================= scalar branch =================
    // dd = vsdir_weight @ x_c
    #pragma unroll
    for (int j = 0; j < OP2; j++) { aX[j] = 0ull; aY[j] = 0ull; aZ[j] = 0ull; }
    #pragma unroll 2
    for (int c = 0; c < CC; c++) {
        float xx = A[(3 * c + 0) * TN + nl];
        float xy = A[(3 * c + 1) * TN + nl];
        float xz = A[(3 * c + 2) * TN + nl];
        unsigned long long xx2, xy2, xz2;
        PACK_DUP(xx2, xx); PACK_DUP(xy2, xy); PACK_DUP(xz2, xz);
        unsigned long long w2[OP2]; load_w8x2(&g_vsdWt[c * CC + ob], w2);
        #pragma unroll
        for (int j = 0; j < OP2; j++) {
            FMA2(aX[j], w2[j], xx2);
            FMA2(aY[j], w2[j], xy2);
            FMA2(aZ[j], w2[j], xz2);
        }
    }
    #pragma unroll
    for (int j = 0; j < OP2; j++) {
        ux[2*j] = lo2(aX[j]); ux[2*j+1] = hi2(aX[j]);
        uy[2*j] = lo2(aY[j]); uy[2*j+1] = hi2(aY[j]);
        uz[2*j] = lo2(aZ[j]); uz[2*j+1] = hi2(aZ[j]);
    }
    {
        float pq = 0;
        #pragma unroll
        for (int j = 0; j < OPT; j++) {
            float n2 = ux[j] * ux[j] + uy[j] * uy[j] + uz[j] * uz[j];
            float inv = 1.f / fmaxf(sqrtf(n2), EPSV);
            int o = ob + j;
            float q = (A[(3 * o + 0) * TN + nl] * ux[j] +
                       A[(3 * o + 1) * TN + nl] * uy[j] +
                       A[(3 * o + 2) * TN + nl] * uz[j]) * inv;
            tv[j] = q;
            pq += q * q;
        }
        red[og * TN + nl] = pq;
    }
    __syncthreads();
    float Q = 0;
    #pragma unroll
    for (int g = 0; g < 8; g++) Q += red[g * TN + nl];
    __syncthreads();
    const float qinv = 1.f / fmaxf(sqrtf(Q), EPSV);
    #pragma unroll
    for (int j = 0; j < OPT; j++)
        Bm[(CC + ob + j) * TN + nl] = tv[j] * qinv;
    __syncthreads();

    // s_out = vs_W @ p + vs_b + ss_W @ s + ss_b
    {
        unsigned long long so2[OP2];
        #pragma unroll
        for (int j = 0; j < OP2; j++)
            so2[j] = pack2(vs_b[ob + 2*j]     + ss_b[ob + 2*j],
                           vs_b[ob + 2*j + 1] + ss_b[ob + 2*j + 1]);
        #pragma unroll 2
        for (int c = 0; c < CC; c++) {
            float p = Bm[(CC + c) * TN + nl];
            float s = Bm[c * TN + nl];
            unsigned long long p2, s2;
            PACK_DUP(p2, p); PACK_DUP(s2, s);
            unsigned long long wva[OP2], wvb[OP2];
            load_w8x2(&g_vsWt[c * CC + ob], wva);
            load_w8x2(&g_ssWt[c * CC + ob], wvb);
            #pragma unroll
            for (int j = 0; j < OP2; j++) {
                FMA2(so2[j], wva[j], p2);
                FMA2(so2[j], wvb[j], s2);
            }
        }
        float* outs = out + (size_t)B * CC * 3 * NPTS + ((size_t)b * CC) * NPTS + n0 + nl;
        #pragma unroll
        for (int j = 0; j < OP2; j++) {
            outs[(size_t)(ob + 2*j) * NPTS]     = lo2(so2[j]);
            outs[(size_t)(ob + 2*j + 1) * NPTS] = hi2(so2[j]);
        }
    }

    // ---- t = sv_W @ s + sv_b ----
    {
        unsigned long long t2[OP2];
        #pragma unroll
        for (int j = 0; j < OP2; j++)
            t2[j] = pack2(sv_b[ob + 2*j], sv_b[ob + 2*j + 1]);
        #pragma unroll 2
        for (int c = 0; c < CC; c++) {
            float s = Bm[c * TN + nl];
            unsigned long long s2; PACK_DUP(s2, s);
            unsigned long long w2[OP2]; load_w8x2(&g_svWt[c * CC + ob], w2);
            #pragma unroll
            for (int j = 0; j < OP2; j++) FMA2(t2[j], w2[j], s2);
        }
        #pragma unroll
        for (int j = 0; j < OP2; j++) { tv[2*j] = lo2(t2[j]); tv[2*j+1] = hi2(t2[j]); }
    }

    // ================= vector branch =================
    // ---- u_c = W1 @ x_c ----
    #pragma unroll
    for (int j = 0; j < OP2; j++) { aX[j] = 0ull; aY[j] = 0ull; aZ[j] = 0ull; }
    #pragma unroll 2
    for (int c = 0; c < CC; c++) {
        float xx = A[(3 * c + 0) * TN + nl];
        float xy = A[(3 * c + 1) * TN + nl];
        float xz = A[(3 * c + 2) * TN + nl];
        unsigned long long xx2, xy2, xz2;
        PACK_DUP(xx2, xx); PACK_DUP(xy2, xy); PACK_DUP(xz2, xz);
        unsigned long long w2[OP2]; load_w8x2(&g_W1t[c * CC + ob], w2);
        #pragma unroll
        for (int j = 0; j < OP2; j++) {
            FMA2(aX[j], w2[j], xx2);
            FMA2(aY[j], w2[j], xy2);
            FMA2(aZ[j], w2[j], xz2);
        }
    }
    #pragma unroll
    for (int j = 0; j < OP2; j++) {
        ux[2*j] = lo2(aX[j]); ux[2*j+1] = hi2(aX[j]);
        uy[2*j] = lo2(aY[j]); uy[2*j+1] = hi2(aY[j]);
        uz[2*j] = lo2(aZ[j]); uz[2*j+1] = hi2(aZ[j]);
    }
    {
        float px = 0, py = 0, pz = 0, pt = 0;
        #pragma unroll
        for (int j = 0; j < OPT; j++) { px += ux[j]; py += uy[j]; pz += uz[j]; pt += tv[j] * tv[j]; }
        red[(og * 6 + 0) * TN + nl] = px; red[(og * 6 + 1) * TN + nl] = py;
        red[(og * 6 + 2) * TN + nl] = pz; red[(og * 6 + 3) * TN + nl] = pt;
    }
    __syncthreads();
    float mux = 0, muy = 0, muz = 0, tss = 0;
    #pragma unroll
    for (int g = 0; g < 8; g++) {
        mux += red[(g * 6 + 0) * TN + nl]; muy += red[(g * 6 + 1) * TN + nl];
        muz += red[(g * 6 + 2) * TN + nl]; tss += red[(g * 6 + 3) * TN + nl];
    }
    __syncthreads();
    mux *= (1.f / CC); muy *= (1.f / CC); muz *= (1.f / CC);
    const float tinv = 1.f / fmaxf(sqrtf(tss), EPSV);

    // v1 = (u_c - mu)*s2v + (mu + m) -> Bm; partial v1-mean
    float p1x = 0, p1y = 0, p1z = 0;
    #pragma unroll
    for (int j = 0; j < OPT; j++) {
        float s2v = tv[j] * tinv;
        float ax = fmaf(ux[j] - mux, s2v, mux + mx);
        float ay = fmaf(uy[j] - muy, s2v, muy + my);
        float az = fmaf(uz[j] - muz, s2v, muz + mz);
        int o = ob + j;
        Bm[(3 * o + 0) * TN + nl] = ax;
        Bm[(3 * o + 1) * TN + nl] = ay;
        Bm[(3 * o + 2) * TN + nl] = az;
        p1x += ax; p1y += ay; p1z += az;
    }

    // ---- d_c = W2 @ x_c ----
    #pragma unroll
    for (int j = 0; j < OP2; j++) { aX[j] = 0ull; aY[j] = 0ull; aZ[j] = 0ull; }
    #pragma unroll 2
    for (int c = 0; c < CC; c++) {
        float xx = A[(3 * c + 0) * TN + nl];
        float xy = A[(3 * c + 1) * TN + nl];
        float xz = A[(3 * c + 2) * TN + nl];
        unsigned long long xx2, xy2, xz2;
        PACK_DUP(xx2, xx); PACK_DUP(xy2, xy); PACK_DUP(xz2, xz);
        unsigned long long w2[OP2]; load_w8x2(&g_W2t[c * CC + ob], w2);
        #pragma unroll
        for (int j = 0; j < OP2; j++) {
            FMA2(aX[j], w2[j], xx2);
            FMA2(aY[j], w2[j], xy2);
            FMA2(aZ[j], w2[j], xz2);
        }
    }
    #pragma unroll
    for (int j = 0; j < OP2; j++) {
        ux[2*j] = lo2(aX[j]); ux[2*j+1] = hi2(aX[j]);
        uy[2*j] = lo2(aY[j]); uy[2*j+1] = hi2(aY[j]);
        uz[2*j] = lo2(aZ[j]); uz[2*j+1] = hi2(aZ[j]);
    }
    {
        float px = 0, py = 0, pz = 0;
        #pragma unroll
        for (int j = 0; j < OPT; j++) { px += ux[j]; py += uy[j]; pz += uz[j]; }
        red[(og * 6 + 0) * TN + nl] = px;  red[(og * 6 + 1) * TN + nl] = py;
        red[(og * 6 + 2) * TN + nl] = pz;  red[(og * 6 + 3) * TN + nl] = p1x;
        red[(og * 6 + 4) * TN + nl] = p1y; red[(og * 6 + 5) * TN + nl] = p1z;
    }
    __syncthreads();
    float dmx = 0, dmy = 0, dmz = 0, m1x = 0, m1y = 0, m1z = 0;
    #pragma unroll
    for (int g = 0; g < 8; g++) {
        dmx += red[(g * 6 + 0) * TN + nl]; dmy += red[(g * 6 + 1) * TN + nl];
        dmz += red[(g * 6 + 2) * TN + nl]; m1x += red[(g * 6 + 3) * TN + nl];
        m1y += red[(g * 6 + 4) * TN + nl]; m1z += red[(g * 6 + 5) * TN + nl];
    }
    __syncthreads();
    dmx *= (1.f / CC); dmy *= (1.f / CC); dmz *= (1.f / CC);
    m1x *= (1.f / CC); m1y *= (1.f / CC); m1z *= (1.f / CC);

    float ny[OPT];
    {
        float pl = 0;
        #pragma unroll
        for (int j = 0; j < OPT; j++) {
            ux[j] -= dmx; uy[j] -= dmy; uz[j] -= dmz;
            float n2 = ux[j] * ux[j] + uy[j] * uy[j] + uz[j] * uz[j];
            ny[j] = sqrtf(n2);
            pl += n2;
        }
        red[og * TN + nl] = pl;
    }
    __syncthreads();
    float L = 0;
    #pragma unroll
    for (int g = 0; g < 8; g++) L += red[g * TN + nl];
    __syncthreads();
    const float linv = 1.f / fmaxf(sqrtf(L), EPSV);

    // ---- v_cross -> A ----
    #pragma unroll
    for (int j = 0; j < OPT; j++) {
        float cf = (ny[j] * linv) / fmaxf(ny[j], EPSV);
        float ex = ux[j] * cf, ey = uy[j] * cf, ez = uz[j] * cf;
        int o = ob + j;
        float ax = Bm[(3 * o + 0) * TN + nl];
        float ay = Bm[(3 * o + 1) * TN + nl];
        float az = Bm[(3 * o + 2) * TN + nl];
        float wx = ax - m1x, wy = ay - m1y, wz = az - m1z;
        A[(3 * o + 0) * TN + nl] = ey * wz - ez * wy + ax;
        A[(3 * o + 1) * TN + nl] = ez * wx - ex * wz + ay;
        A[(3 * o + 2) * TN + nl] = ex * wy - ey * wx + az;
    }
    __syncthreads();

    // ---- v_out = W3[:, :128] @ v_cross (A) + W3[:, 128:] @ v1 (Bm) ----
    #pragma unroll
    for (int j = 0; j < OP2; j++) { aX[j] = 0ull; aY[j] = 0ull; aZ[j] = 0ull; }
    #pragma unroll 2
    for (int c = 0; c < CC; c++) {
        float xx = A[(3 * c + 0) * TN + nl];
        float xy = A[(3 * c + 1) * TN + nl];
        float xz = A[(3 * c + 2) * TN + nl];
        unsigned long long xx2, xy2, xz2;
        PACK_DUP(xx2, xx); PACK_DUP(xy2, xy); PACK_DUP(xz2, xz);
        unsigned long long w2[OP2]; load_w8x2(&g_W3t[c * CC + ob], w2);
        #pragma unroll
        for (int j = 0; j < OP2; j++) {
            FMA2(aX[j], w2[j], xx2);
            FMA2(aY[j], w2[j], xy2);
            FMA2(aZ[j], w2[j], xz2);
        }
    }
    #pragma unroll 2
    for (int c = 0; c < CC; c++) {
        float xx = Bm[(3 * c + 0) * TN + nl];
        float xy = Bm[(3 * c + 1) * TN + nl];
        float xz = Bm[(3 * c + 2) * TN + nl];
        unsigned long long xx2, xy2, xz2;
        PACK_DUP(xx2, xx); PACK_DUP(xy2, xy); PACK_DUP(xz2, xz);
        unsigned long long w2[OP2]; load_w8x2(&g_W3t[(CC + c) * CC + ob], w2);
        #pragma unroll
        for (int j = 0; j < OP2; j++) {
            FMA2(aX[j], w2[j], xx2);
            FMA2(aY[j], w2[j], xy2);
            FMA2(aZ[j], w2[j], xz2);
        }
    }
    {
        float* outv = out + ((size_t)b * CC) * 3 * NPTS + n0 + nl;
        #pragma unroll
        for (int j = 0; j < OP2; j++) {
            int o = ob + 2 * j;
            outv[(size_t)(3 * o + 0) * NPTS] = lo2(aX[j]);
            outv[(size_t)(3 * o + 1) * NPTS] = lo2(aY[j]);
            outv[(size_t)(3 * o + 2) * NPTS] = lo2(aZ[j]);
            outv[(size_t)(3 * o + 3) * NPTS] = hi2(aX[j]);
            outv[(size_t)(3 * o + 4) * NPTS] = hi2(aY[j]);
            outv[(size_t)(3 * o + 5) * NPTS] = hi2(aZ[j]);
        }
    }
}

extern "C" void kernel_launch(void* const* d_in, const int* in_sizes, int n_in,
                              void* d_out, int out_size)
{
    const float* v_in      = (const float*)d_in[0];
    const float* s_in      = (const float*)d_in[1];
    const float* weight    = (const float*)d_in[2];
    const float* sv_W      = (const float*)d_in[3];
    const float* sv_b      = (const float*)d_in[4];
    const float* cross_w   = (const float*)d_in[5];
    const float* crossfc_w = (const float*)d_in[6];
    const float* vsdir_w   = (const float*)d_in[7];
    const float* vs_W      = (const float*)d_in[8];
    const float* vs_b      = (const float*)d_in[9];
    const float* ss_W      = (const float*)d_in[10];
    const float* ss_b      = (const float*)d_in[11];
    float* out = (float*)d_out;

    const int B = in_sizes[0] / (CC * 3 * NPTS);   // 16

    prep_kernel<<<CC, CC>>>(weight, sv_W, cross_w, crossfc_w, vsdir_w, vs_W, ss_W);

    const size_t smem = (size_t)(6 * CC * TN + 48 * TN) * sizeof(float); // 104,448 B
    cudaFuncSetAttribute(fused_kernel, cudaFuncAttributeMaxDynamicSharedMemorySize, (int)smem);
    fused_kernel<<<B * (NPTS / TN), 256, smem>>>(v_in, s_in, sv_b, vs_b, ss_b, out, B);
}